// round 10
// baseline (speedup 1.0000x reference)
#include <cuda_runtime.h>
#include <cuda_fp16.h>
#include <cstdint>

#define NMAX 100000
#define EMAX 3200000
#define F 128
#define FP8_SCALE 16.0f

typedef unsigned short bf16_t;

// Scratch (device globals — no allocation allowed)
__device__ int     g_cnt   [NMAX];
__device__ int     g_start [NMAX + 1];
__device__ int     g_cursor[NMAX];
__device__ int     g_bsum  [256];
__device__ int     g_boff  [256];
__device__ int     g_srow  [EMAX];              // edge row-ids sorted by col
__device__ float   g_dinv  [NMAX];
__device__ uint8_t g_h8    [(size_t)NMAX * F];  // layer GEMM out: fp8, prescaled dinv*16
__device__ uint8_t g_h8b   [(size_t)NMAX * F];  // layer-2 GEMM out (separate to avoid WAR)

// ---------------------------------------------------------------------------
// numeric helpers
// ---------------------------------------------------------------------------
__device__ __forceinline__ uint32_t f2_to_bf2(float lo, float hi) {
    uint32_t r;
    asm("cvt.rn.bf16x2.f32 %0, %1, %2;" : "=r"(r) : "f"(hi), "f"(lo));
    return r;
}

__device__ __forceinline__ uint16_t f2_to_e4m3x2(float lo, float hi) {
    uint16_t r;
    asm("cvt.rn.satfinite.e4m3x2.f32 %0, %1, %2;" : "=h"(r) : "f"(hi), "f"(lo));
    return r;
}

__device__ __forceinline__ __half2 e4m3x2_to_h2(uint16_t v) {
    uint32_t r;
    asm("cvt.rn.f16x2.e4m3x2 %0, %1;" : "=r"(r) : "h"(v));
    return *(__half2*)&r;
}

__device__ __forceinline__ void fp8x4_to_h2(uint32_t u, __half2& p0, __half2& p1) {
    p0 = e4m3x2_to_h2((uint16_t)(u & 0xFFFFu));
    p1 = e4m3x2_to_h2((uint16_t)(u >> 16));
}

// ---------------------------------------------------------------------------
// degree histogram / dinv
// ---------------------------------------------------------------------------
__global__ void k_hist(const int* __restrict__ col, int* __restrict__ cnt, int E) {
    int i = blockIdx.x * blockDim.x + threadIdx.x;
    if (i < E) atomicAdd(&cnt[col[i]], 1);
}

__global__ void k_dinv(const int* __restrict__ cnt, float* __restrict__ dinv, int n) {
    int i = blockIdx.x * blockDim.x + threadIdx.x;
    if (i < n) dinv[i] = rsqrtf((float)(cnt[i] + 1));  // +1 self-loop
}

// ---------------------------------------------------------------------------
// Counting sort of edges by col
// ---------------------------------------------------------------------------
#define SCAN_BLK 1024

__global__ void k_blocksum(const int* __restrict__ cnt, int* __restrict__ bsum, int n) {
    __shared__ int sm[256];
    int t = threadIdx.x, b = blockIdx.x;
    int base = b * SCAN_BLK;
    int s = 0;
    #pragma unroll
    for (int k = 0; k < 4; k++) {
        int i = base + t * 4 + k;
        if (i < n) s += cnt[i];
    }
    sm[t] = s; __syncthreads();
    for (int off = 128; off > 0; off >>= 1) {
        if (t < off) sm[t] += sm[t + off];
        __syncthreads();
    }
    if (t == 0) bsum[b] = sm[0];
}

__global__ void k_scanbsum(const int* __restrict__ bsum, int* __restrict__ boff,
                           int* __restrict__ start, int nb, int n) {
    __shared__ int sm[256];
    int t = threadIdx.x;
    int v = (t < nb) ? bsum[t] : 0;
    sm[t] = v; __syncthreads();
    #pragma unroll
    for (int off = 1; off < 256; off <<= 1) {
        int x = 0;
        if (t >= off) x = sm[t - off];
        __syncthreads();
        sm[t] += x;
        __syncthreads();
    }
    if (t < nb) boff[t] = sm[t] - v;
    if (t == 255) start[n] = sm[255];
}

__global__ void k_writestart(const int* __restrict__ cnt, const int* __restrict__ boff,
                             int* __restrict__ start, int* __restrict__ cursor, int n) {
    __shared__ int sm[256];
    int t = threadIdx.x, b = blockIdx.x;
    int base = b * SCAN_BLK + t * 4;
    int c[4]; int s = 0;
    #pragma unroll
    for (int k = 0; k < 4; k++) {
        c[k] = (base + k < n) ? cnt[base + k] : 0;
        s += c[k];
    }
    sm[t] = s; __syncthreads();
    #pragma unroll
    for (int off = 1; off < 256; off <<= 1) {
        int x = 0;
        if (t >= off) x = sm[t - off];
        __syncthreads();
        sm[t] += x;
        __syncthreads();
    }
    int excl = boff[b] + sm[t] - s;
    #pragma unroll
    for (int k = 0; k < 4; k++) {
        int i = base + k;
        if (i < n) { start[i] = excl; cursor[i] = excl; }
        excl += c[k];
    }
}

__global__ void k_scatter(const int* __restrict__ row, const int* __restrict__ col,
                          int* __restrict__ cursor, int* __restrict__ srow, int E) {
    int i = blockIdx.x * blockDim.x + threadIdx.x;
    if (i >= E) return;
    int c = col[i];
    int pos = atomicAdd(&cursor[c], 1);
    srow[pos] = row[i];
}

// ---------------------------------------------------------------------------
// shared MMA plumbing
// ---------------------------------------------------------------------------
#define SLD 136

__device__ __forceinline__ uint32_t smem_u32(const void* p) {
    return (uint32_t)__cvta_generic_to_shared(p);
}

__device__ __forceinline__ void ldsm_x4(uint32_t* r, uint32_t addr) {
    asm volatile("ldmatrix.sync.aligned.m8n8.x4.shared.b16 {%0,%1,%2,%3}, [%4];"
                 : "=r"(r[0]), "=r"(r[1]), "=r"(r[2]), "=r"(r[3]) : "r"(addr));
}

__device__ __forceinline__ void ldsm_x4_t(uint32_t* r, uint32_t addr) {
    asm volatile("ldmatrix.sync.aligned.m8n8.x4.trans.shared.b16 {%0,%1,%2,%3}, [%4];"
                 : "=r"(r[0]), "=r"(r[1]), "=r"(r[2]), "=r"(r[3]) : "r"(addr));
}

__device__ __forceinline__ void mma_bf16(float* c, const uint32_t* a,
                                         uint32_t b0, uint32_t b1) {
    asm volatile(
        "mma.sync.aligned.m16n8k16.row.col.f32.bf16.bf16.f32 "
        "{%0,%1,%2,%3}, {%4,%5,%6,%7}, {%8,%9}, {%0,%1,%2,%3};"
        : "+f"(c[0]), "+f"(c[1]), "+f"(c[2]), "+f"(c[3])
        : "r"(a[0]), "r"(a[1]), "r"(a[2]), "r"(a[3]), "r"(b0), "r"(b1));
}

__device__ __forceinline__ uint2 load_row4(const float* base, int c4) {
    float4 v = __ldg((const float4*)base + c4);
    uint2 u;
    u.x = f2_to_bf2(v.x, v.y);
    u.y = f2_to_bf2(v.z, v.w);
    return u;
}

// MMA mainloop + fp8 epilogue over smem tiles As/Ws (both 128 x SLD bf16).
__device__ __forceinline__ void mma_main_and_store(
    const bf16_t* As, const bf16_t* Ws, const float* __restrict__ dinv,
    uint8_t* __restrict__ H8, float esc, int block_row, int M,
    int wid, int lane) {
    const int wm = (wid & 3) * 32;
    const int wn = (wid >> 2) * 64;

    float acc[2][8][4];
    #pragma unroll
    for (int mt = 0; mt < 2; mt++)
        #pragma unroll
        for (int nt = 0; nt < 8; nt++)
            #pragma unroll
            for (int q = 0; q < 4; q++) acc[mt][nt][q] = 0.f;

    const uint32_t As_b = smem_u32(As);
    const uint32_t Ws_b = smem_u32(Ws);
    const int lrow = lane & 15;
    const int lcol = (lane >> 4) * 8;

    #pragma unroll
    for (int kb = 0; kb < 8; kb++) {
        uint32_t a[2][4];
        #pragma unroll
        for (int mt = 0; mt < 2; mt++) {
            int row = wm + mt * 16 + lrow;
            int col = kb * 16 + lcol;
            ldsm_x4(a[mt], As_b + (row * SLD + col) * 2);
        }
        uint32_t b[8][2];
        #pragma unroll
        for (int np = 0; np < 4; np++) {
            int krow = kb * 16 + lrow;
            int ncol = wn + np * 16 + lcol;
            uint32_t r[4];
            ldsm_x4_t(r, Ws_b + (krow * SLD + ncol) * 2);
            b[np * 2][0] = r[0]; b[np * 2][1] = r[1];
            b[np * 2 + 1][0] = r[2]; b[np * 2 + 1][1] = r[3];
        }
        #pragma unroll
        for (int mt = 0; mt < 2; mt++)
            #pragma unroll
            for (int nt = 0; nt < 8; nt++)
                mma_bf16(acc[mt][nt], a[mt], b[nt][0], b[nt][1]);
    }

    #pragma unroll
    for (int mt = 0; mt < 2; mt++) {
        int r0 = block_row + wm + mt * 16 + (lane >> 2);
        int r1 = r0 + 8;
        float d0 = __ldg(dinv + min(r0, M - 1)) * esc;
        float d1 = __ldg(dinv + min(r1, M - 1)) * esc;
        #pragma unroll
        for (int nt = 0; nt < 8; nt++) {
            int col = wn + nt * 8 + (lane & 3) * 2;
            if (r0 < M)
                *(uint16_t*)(H8 + (size_t)r0 * F + col) =
                    f2_to_e4m3x2(acc[mt][nt][0] * d0, acc[mt][nt][1] * d0);
            if (r1 < M)
                *(uint16_t*)(H8 + (size_t)r1 * F + col) =
                    f2_to_e4m3x2(acc[mt][nt][2] * d1, acc[mt][nt][3] * d1);
        }
    }
}

// ---------------------------------------------------------------------------
// GEMM1: H8 = (x @ W1) * dinv * 16   (x fp32 from DRAM)
// ---------------------------------------------------------------------------
__global__ void __launch_bounds__(256, 2)
k_gemm_mma(const float* __restrict__ A, const float* __restrict__ W,
           const float* __restrict__ dinv, uint8_t* __restrict__ H8,
           float esc, int M) {
    extern __shared__ bf16_t smh[];
    bf16_t* As = smh;
    bf16_t* Ws = smh + 128 * SLD;

    const int tid = threadIdx.x;
    const int block_row = blockIdx.x * 128;

    #pragma unroll 4
    for (int i = tid; i < 4096; i += 256) {
        int r = i >> 5, c4 = i & 31;
        *(uint2*)(Ws + r * SLD + c4 * 4) = load_row4(W + r * F, c4);
    }
    #pragma unroll 4
    for (int i = tid; i < 4096; i += 256) {
        int r = i >> 5, c4 = i & 31;
        int gr = block_row + r;
        uint2 u = make_uint2(0u, 0u);
        if (gr < M) u = load_row4(A + (size_t)gr * F, c4);
        *(uint2*)(As + r * SLD + c4 * 4) = u;
    }
    __syncthreads();

    mma_main_and_store(As, Ws, dinv, H8, esc, block_row, M,
                       tid >> 5, tid & 31);
}

// ---------------------------------------------------------------------------
// agg edge-sum helpers
// ---------------------------------------------------------------------------
__device__ __forceinline__ void tree4_acc(uint32_t u0, uint32_t u1,
                                          uint32_t u2, uint32_t u3, float4& acc) {
    __half2 a0, b0, a1, b1, a2, b2, a3, b3;
    fp8x4_to_h2(u0, a0, b0);
    fp8x4_to_h2(u1, a1, b1);
    fp8x4_to_h2(u2, a2, b2);
    fp8x4_to_h2(u3, a3, b3);
    __half2 sa = __hadd2(__hadd2(a0, a1), __hadd2(a2, a3));
    __half2 sb = __hadd2(__hadd2(b0, b1), __hadd2(b2, b3));
    float2 fa = __half22float2(sa), fb = __half22float2(sb);
    acc.x += fa.x; acc.y += fa.y; acc.z += fb.x; acc.w += fb.y;
}

// Aggregate one node's neighbor rows (fp8 H8, 128B rows). Warp-collective.
__device__ __forceinline__ float4 agg_node(
    const int* __restrict__ start, const int* __restrict__ srow,
    const uint8_t* __restrict__ H8, int c, int lane) {
    int beg = __ldg(start + c);
    int end = __ldg(start + c + 1);

    uint32_t su = __ldg((const uint32_t*)(H8 + (size_t)c * F) + lane);
    __half2 spa, spb; fp8x4_to_h2(su, spa, spb);
    float2 sfa = __half22float2(spa), sfb = __half22float2(spb);
    float4 acc = make_float4(sfa.x, sfa.y, sfb.x, sfb.y);

    for (int i = beg; i < end; i += 32) {
        int idx = i + lane;
        int rr = __ldg(srow + (idx < end ? idx : end - 1));
        int cnt = min(end - i, 32);
        int j = 0;
        for (; j + 8 <= cnt; j += 8) {
            int r0 = __shfl_sync(0xFFFFFFFFu, rr, j);
            int r1 = __shfl_sync(0xFFFFFFFFu, rr, j + 1);
            int r2 = __shfl_sync(0xFFFFFFFFu, rr, j + 2);
            int r3 = __shfl_sync(0xFFFFFFFFu, rr, j + 3);
            int r4 = __shfl_sync(0xFFFFFFFFu, rr, j + 4);
            int r5 = __shfl_sync(0xFFFFFFFFu, rr, j + 5);
            int r6 = __shfl_sync(0xFFFFFFFFu, rr, j + 6);
            int r7 = __shfl_sync(0xFFFFFFFFu, rr, j + 7);
            uint32_t u0 = __ldg((const uint32_t*)(H8 + (size_t)r0 * F) + lane);
            uint32_t u1 = __ldg((const uint32_t*)(H8 + (size_t)r1 * F) + lane);
            uint32_t u2 = __ldg((const uint32_t*)(H8 + (size_t)r2 * F) + lane);
            uint32_t u3 = __ldg((const uint32_t*)(H8 + (size_t)r3 * F) + lane);
            uint32_t u4 = __ldg((const uint32_t*)(H8 + (size_t)r4 * F) + lane);
            uint32_t u5 = __ldg((const uint32_t*)(H8 + (size_t)r5 * F) + lane);
            uint32_t u6 = __ldg((const uint32_t*)(H8 + (size_t)r6 * F) + lane);
            uint32_t u7 = __ldg((const uint32_t*)(H8 + (size_t)r7 * F) + lane);
            tree4_acc(u0, u1, u2, u3, acc);
            tree4_acc(u4, u5, u6, u7, acc);
        }
        for (; j + 4 <= cnt; j += 4) {
            int r0 = __shfl_sync(0xFFFFFFFFu, rr, j);
            int r1 = __shfl_sync(0xFFFFFFFFu, rr, j + 1);
            int r2 = __shfl_sync(0xFFFFFFFFu, rr, j + 2);
            int r3 = __shfl_sync(0xFFFFFFFFu, rr, j + 3);
            uint32_t u0 = __ldg((const uint32_t*)(H8 + (size_t)r0 * F) + lane);
            uint32_t u1 = __ldg((const uint32_t*)(H8 + (size_t)r1 * F) + lane);
            uint32_t u2 = __ldg((const uint32_t*)(H8 + (size_t)r2 * F) + lane);
            uint32_t u3 = __ldg((const uint32_t*)(H8 + (size_t)r3 * F) + lane);
            tree4_acc(u0, u1, u2, u3, acc);
        }
        for (; j < cnt; j++) {
            int r0 = __shfl_sync(0xFFFFFFFFu, rr, j);
            uint32_t u0 = __ldg((const uint32_t*)(H8 + (size_t)r0 * F) + lane);
            __half2 pa, pb; fp8x4_to_h2(u0, pa, pb);
            float2 fa = __half22float2(pa), fb = __half22float2(pb);
            acc.x += fa.x; acc.y += fa.y; acc.z += fb.x; acc.w += fb.y;
        }
    }
    return acc;
}

// ---------------------------------------------------------------------------
// FUSED agg1 + GEMM2: per CTA, aggregate 128 nodes' rows into the smem A-tile
// (bf16, relu'd, bias added), then run the MMA mainloop with W2 and store fp8.
// ---------------------------------------------------------------------------
__global__ void __launch_bounds__(256, 2)
k_agg_gemm(const int* __restrict__ start, const int* __restrict__ srow,
           const float* __restrict__ dinv, const uint8_t* __restrict__ H8in,
           const float* __restrict__ bias, const float* __restrict__ W,
           uint8_t* __restrict__ H8out, int M) {
    extern __shared__ bf16_t smh[];
    bf16_t* As = smh;
    bf16_t* Ws = smh + 128 * SLD;

    const int tid = threadIdx.x;
    const int wid = tid >> 5, lane = tid & 31;
    const int block_row = blockIdx.x * 128;

    // Load W2 into smem (independent of agg writes)
    #pragma unroll 4
    for (int i = tid; i < 4096; i += 256) {
        int r = i >> 5, c4 = i & 31;
        *(uint2*)(Ws + r * SLD + c4 * 4) = load_row4(W + r * F, c4);
    }

    // Phase 1: each warp aggregates 16 nodes into As rows (bf16, relu+bias)
    float4 bv = __ldg((const float4*)bias + lane);
    #pragma unroll 1
    for (int k = 0; k < 16; k++) {
        int lr = wid * 16 + k;
        int c = block_row + lr;
        uint2 u = make_uint2(0u, 0u);
        if (c < M) {
            float dc = __ldg(dinv + c) * (1.0f / FP8_SCALE);
            float4 acc = agg_node(start, srow, H8in, c, lane);
            float ox = fmaxf(fmaf(dc, acc.x, bv.x), 0.f);
            float oy = fmaxf(fmaf(dc, acc.y, bv.y), 0.f);
            float oz = fmaxf(fmaf(dc, acc.z, bv.z), 0.f);
            float ow = fmaxf(fmaf(dc, acc.w, bv.w), 0.f);
            u.x = f2_to_bf2(ox, oy);
            u.y = f2_to_bf2(oz, ow);
        }
        *(uint2*)(As + lr * SLD + lane * 4) = u;
    }
    __syncthreads();

    // Phase 2: MMA + fp8 epilogue (As holds unscaled relu(a) -> esc = 16)
    mma_main_and_store(As, Ws, dinv, H8out, FP8_SCALE, block_row, M, wid, lane);
}

// ---------------------------------------------------------------------------
// agg2 + fused head: out[c] = sigmoid(dot(relu(dc/16*sum + b2), Wl) + bl)
// ---------------------------------------------------------------------------
#define NPW 4

__global__ void __launch_bounds__(256)
k_agg_head(const int* __restrict__ start, const int* __restrict__ srow,
           const float* __restrict__ dinv, const uint8_t* __restrict__ H8,
           const float* __restrict__ bias,
           const float* __restrict__ Wl, const float* __restrict__ bl,
           float* __restrict__ fout, int n) {
    const int lane = threadIdx.x & 31;
    const int warp = (blockIdx.x * blockDim.x + threadIdx.x) >> 5;
    int c0 = warp * NPW;
    if (c0 >= n) return;
    int c_end = min(c0 + NPW, n);

    float4 bv = __ldg((const float4*)bias + lane);
    float4 wv = __ldg((const float4*)Wl + lane);
    float blv = __ldg(bl);

    for (int c = c0; c < c_end; c++) {
        float dc = __ldg(dinv + c) * (1.0f / FP8_SCALE);
        float4 acc = agg_node(start, srow, H8, c, lane);
        float4 o = make_float4(fmaf(dc, acc.x, bv.x), fmaf(dc, acc.y, bv.y),
                               fmaf(dc, acc.z, bv.z), fmaf(dc, acc.w, bv.w));
        float s = fmaxf(o.x, 0.f) * wv.x + fmaxf(o.y, 0.f) * wv.y +
                  fmaxf(o.z, 0.f) * wv.z + fmaxf(o.w, 0.f) * wv.w;
        #pragma unroll
        for (int off = 16; off; off >>= 1) s += __shfl_xor_sync(0xFFFFFFFFu, s, off);
        if (lane == 0) {
            float z = s + blv;
            fout[c] = 1.0f / (1.0f + expf(-z));
        }
    }
}

// ---------------------------------------------------------------------------
extern "C" void kernel_launch(void* const* d_in, const int* in_sizes, int n_in,
                              void* d_out, int out_size) {
    const float* x  = (const float*)d_in[0];
    const int*   ei = (const int*)  d_in[1];
    const float* W1 = (const float*)d_in[2];
    const float* b1 = (const float*)d_in[3];
    const float* W2 = (const float*)d_in[4];
    const float* b2 = (const float*)d_in[5];
    const float* Wl = (const float*)d_in[6];
    const float* bl = (const float*)d_in[7];

    int n = in_sizes[0] / F;
    int E = in_sizes[1] / 2;
    const int* rowp = ei;
    const int* colp = ei + E;

    int *cnt, *start, *cursor, *bsum, *boff, *srow;
    float *dinv;
    uint8_t *h8, *h8b;
    cudaGetSymbolAddress((void**)&cnt,    g_cnt);
    cudaGetSymbolAddress((void**)&start,  g_start);
    cudaGetSymbolAddress((void**)&cursor, g_cursor);
    cudaGetSymbolAddress((void**)&bsum,   g_bsum);
    cudaGetSymbolAddress((void**)&boff,   g_boff);
    cudaGetSymbolAddress((void**)&srow,   g_srow);
    cudaGetSymbolAddress((void**)&dinv,   g_dinv);
    cudaGetSymbolAddress((void**)&h8,     g_h8);
    cudaGetSymbolAddress((void**)&h8b,    g_h8b);

    const size_t gemm_smem = (size_t)(2 * 128 * SLD) * sizeof(bf16_t);
    cudaFuncSetAttribute((const void*)k_gemm_mma,
                         cudaFuncAttributeMaxDynamicSharedMemorySize, (int)gemm_smem);
    cudaFuncSetAttribute((const void*)k_agg_gemm,
                         cudaFuncAttributeMaxDynamicSharedMemorySize, (int)gemm_smem);

    // Side stream + events for overlapping the sort chain with GEMM1.
    static cudaStream_t s2 = nullptr;
    static cudaEvent_t evA = nullptr, evB = nullptr;
    static int init_tried = 0;
    if (!init_tried) {
        init_tried = 1;
        if (cudaStreamCreateWithFlags(&s2, cudaStreamNonBlocking) != cudaSuccess) s2 = nullptr;
        if (cudaEventCreateWithFlags(&evA, cudaEventDisableTiming) != cudaSuccess) evA = nullptr;
        if (cudaEventCreateWithFlags(&evB, cudaEventDisableTiming) != cudaSuccess) evB = nullptr;
    }
    bool par = (s2 != nullptr) && (evA != nullptr) && (evB != nullptr);

    int nb = (n + SCAN_BLK - 1) / SCAN_BLK;
    int gemm_grid = (n + 127) / 128;
    int agg_grid  = ((n + NPW - 1) / NPW * 32 + 255) / 256;

    // --- degree + dinv (cnt zeroed via memset node) ---
    cudaMemsetAsync(cnt, 0, (size_t)n * sizeof(int), 0);
    k_hist<<<(E + 255) / 256, 256>>>(colp, cnt, E);
    k_dinv<<<(n + 255) / 256, 256>>>(cnt, dinv, n);

    if (par) {
        cudaEventRecord(evA, 0);
        cudaStreamWaitEvent(s2, evA, 0);
        k_blocksum<<<nb, 256, 0, s2>>>(cnt, bsum, n);
        k_gemm_mma<<<gemm_grid, 256, gemm_smem>>>(x, W1, dinv, h8, FP8_SCALE, n);
        k_scanbsum  <<<1, 256, 0, s2>>>(bsum, boff, start, nb, n);
        k_writestart<<<nb, 256, 0, s2>>>(cnt, boff, start, cursor, n);
        k_scatter   <<<(E + 255) / 256, 256, 0, s2>>>(rowp, colp, cursor, srow, E);
        cudaEventRecord(evB, s2);
        cudaStreamWaitEvent(0, evB, 0);
    } else {
        k_blocksum  <<<nb, 256>>>(cnt, bsum, n);
        k_gemm_mma<<<gemm_grid, 256, gemm_smem>>>(x, W1, dinv, h8, FP8_SCALE, n);
        k_scanbsum  <<<1, 256>>>(bsum, boff, start, nb, n);
        k_writestart<<<nb, 256>>>(cnt, boff, start, cursor, n);
        k_scatter   <<<(E + 255) / 256, 256>>>(rowp, colp, cursor, srow, E);
    }

    // --- fused agg1 + GEMM2: h8b = 16*dinv*(relu(agg(h8)+b1) @ W2) ---
    k_agg_gemm<<<gemm_grid, 256, gemm_smem>>>(start, srow, dinv, h8, b1, W2, h8b, n);

    // --- agg2 + head ---
    k_agg_head<<<agg_grid, 256>>>(start, srow, dinv, h8b, b2, Wl, bl, (float*)d_out, n);
}

// round 11
// speedup vs baseline: 1.1591x; 1.1591x over previous
#include <cuda_runtime.h>
#include <cuda_fp16.h>
#include <cstdint>

#define NMAX 100000
#define EMAX 3200000
#define F 128
#define FP8_SCALE 16.0f

typedef unsigned short bf16_t;

// Scratch (device globals — no allocation allowed)
__device__ int     g_cnt   [NMAX];
__device__ int     g_start [NMAX + 1];
__device__ int     g_cursor[NMAX];
__device__ int     g_bsum  [256];
__device__ int     g_boff  [256];
__device__ int     g_srow  [EMAX];              // edge row-ids sorted by col
__device__ float   g_dinv  [NMAX];
__device__ uint8_t g_h8    [(size_t)NMAX * F];  // GEMM out (both layers): fp8, prescaled dinv*16
__device__ uint8_t g_a8    [(size_t)NMAX * F];  // layer-1 agg output: fp8, relu'd, *16

// ---------------------------------------------------------------------------
// numeric helpers
// ---------------------------------------------------------------------------
__device__ __forceinline__ uint32_t f2_to_bf2(float lo, float hi) {
    uint32_t r;
    asm("cvt.rn.bf16x2.f32 %0, %1, %2;" : "=r"(r) : "f"(hi), "f"(lo));
    return r;
}

__device__ __forceinline__ uint16_t f2_to_e4m3x2(float lo, float hi) {
    uint16_t r;
    asm("cvt.rn.satfinite.e4m3x2.f32 %0, %1, %2;" : "=h"(r) : "f"(hi), "f"(lo));
    return r;
}

__device__ __forceinline__ __half2 e4m3x2_to_h2(uint16_t v) {
    uint32_t r;
    asm("cvt.rn.f16x2.e4m3x2 %0, %1;" : "=r"(r) : "h"(v));
    return *(__half2*)&r;
}

__device__ __forceinline__ void fp8x4_to_h2(uint32_t u, __half2& p0, __half2& p1) {
    p0 = e4m3x2_to_h2((uint16_t)(u & 0xFFFFu));
    p1 = e4m3x2_to_h2((uint16_t)(u >> 16));
}

// 8 packed fp8 (uint2) -> 4 half2
struct H2x4 { __half2 a, b, c, d; };
__device__ __forceinline__ H2x4 fp8x8_to_h2(uint2 u) {
    H2x4 r;
    fp8x4_to_h2(u.x, r.a, r.b);
    fp8x4_to_h2(u.y, r.c, r.d);
    return r;
}

// ---------------------------------------------------------------------------
// degree histogram / dinv
// ---------------------------------------------------------------------------
__global__ void k_hist(const int* __restrict__ col, int* __restrict__ cnt, int E) {
    int i = blockIdx.x * blockDim.x + threadIdx.x;
    if (i < E) atomicAdd(&cnt[col[i]], 1);
}

__global__ void k_dinv(const int* __restrict__ cnt, float* __restrict__ dinv, int n) {
    int i = blockIdx.x * blockDim.x + threadIdx.x;
    if (i < n) dinv[i] = rsqrtf((float)(cnt[i] + 1));  // +1 self-loop
}

// ---------------------------------------------------------------------------
// Counting sort of edges by col
// ---------------------------------------------------------------------------
#define SCAN_BLK 1024

__global__ void k_blocksum(const int* __restrict__ cnt, int* __restrict__ bsum, int n) {
    __shared__ int sm[256];
    int t = threadIdx.x, b = blockIdx.x;
    int base = b * SCAN_BLK;
    int s = 0;
    #pragma unroll
    for (int k = 0; k < 4; k++) {
        int i = base + t * 4 + k;
        if (i < n) s += cnt[i];
    }
    sm[t] = s; __syncthreads();
    for (int off = 128; off > 0; off >>= 1) {
        if (t < off) sm[t] += sm[t + off];
        __syncthreads();
    }
    if (t == 0) bsum[b] = sm[0];
}

__global__ void k_scanbsum(const int* __restrict__ bsum, int* __restrict__ boff,
                           int* __restrict__ start, int nb, int n) {
    __shared__ int sm[256];
    int t = threadIdx.x;
    int v = (t < nb) ? bsum[t] : 0;
    sm[t] = v; __syncthreads();
    #pragma unroll
    for (int off = 1; off < 256; off <<= 1) {
        int x = 0;
        if (t >= off) x = sm[t - off];
        __syncthreads();
        sm[t] += x;
        __syncthreads();
    }
    if (t < nb) boff[t] = sm[t] - v;
    if (t == 255) start[n] = sm[255];
}

__global__ void k_writestart(const int* __restrict__ cnt, const int* __restrict__ boff,
                             int* __restrict__ start, int* __restrict__ cursor, int n) {
    __shared__ int sm[256];
    int t = threadIdx.x, b = blockIdx.x;
    int base = b * SCAN_BLK + t * 4;
    int c[4]; int s = 0;
    #pragma unroll
    for (int k = 0; k < 4; k++) {
        c[k] = (base + k < n) ? cnt[base + k] : 0;
        s += c[k];
    }
    sm[t] = s; __syncthreads();
    #pragma unroll
    for (int off = 1; off < 256; off <<= 1) {
        int x = 0;
        if (t >= off) x = sm[t - off];
        __syncthreads();
        sm[t] += x;
        __syncthreads();
    }
    int excl = boff[b] + sm[t] - s;
    #pragma unroll
    for (int k = 0; k < 4; k++) {
        int i = base + k;
        if (i < n) { start[i] = excl; cursor[i] = excl; }
        excl += c[k];
    }
}

__global__ void k_scatter(const int* __restrict__ row, const int* __restrict__ col,
                          int* __restrict__ cursor, int* __restrict__ srow, int E) {
    int i = blockIdx.x * blockDim.x + threadIdx.x;
    if (i >= E) return;
    int c = col[i];
    int pos = atomicAdd(&cursor[c], 1);
    srow[pos] = row[i];
}

// ---------------------------------------------------------------------------
// Tensor-core GEMM (bf16 mma): H8(fp8) = (A @ W) * dinv[row] * esc
// A may be fp32 (layer 1) or fp8 (layer 2; values carry x16 already, esc=1).
// ---------------------------------------------------------------------------
#define SLD 136

__device__ __forceinline__ uint32_t smem_u32(const void* p) {
    return (uint32_t)__cvta_generic_to_shared(p);
}

__device__ __forceinline__ void ldsm_x4(uint32_t* r, uint32_t addr) {
    asm volatile("ldmatrix.sync.aligned.m8n8.x4.shared.b16 {%0,%1,%2,%3}, [%4];"
                 : "=r"(r[0]), "=r"(r[1]), "=r"(r[2]), "=r"(r[3]) : "r"(addr));
}

__device__ __forceinline__ void ldsm_x4_t(uint32_t* r, uint32_t addr) {
    asm volatile("ldmatrix.sync.aligned.m8n8.x4.trans.shared.b16 {%0,%1,%2,%3}, [%4];"
                 : "=r"(r[0]), "=r"(r[1]), "=r"(r[2]), "=r"(r[3]) : "r"(addr));
}

__device__ __forceinline__ void mma_bf16(float* c, const uint32_t* a,
                                         uint32_t b0, uint32_t b1) {
    asm volatile(
        "mma.sync.aligned.m16n8k16.row.col.f32.bf16.bf16.f32 "
        "{%0,%1,%2,%3}, {%4,%5,%6,%7}, {%8,%9}, {%0,%1,%2,%3};"
        : "+f"(c[0]), "+f"(c[1]), "+f"(c[2]), "+f"(c[3])
        : "r"(a[0]), "r"(a[1]), "r"(a[2]), "r"(a[3]), "r"(b0), "r"(b1));
}

__device__ __forceinline__ uint2 load_row4(const float* base, int c4) {
    float4 v = __ldg((const float4*)base + c4);
    uint2 u;
    u.x = f2_to_bf2(v.x, v.y);
    u.y = f2_to_bf2(v.z, v.w);
    return u;
}

// fp8 row load: 4 e4m3 -> bf16x2 pair (exact: e4m3 mantissa fits bf16)
__device__ __forceinline__ uint2 load_row4(const uint8_t* base, int c4) {
    uint32_t u = __ldg((const uint32_t*)base + c4);
    __half2 p0, p1; fp8x4_to_h2(u, p0, p1);
    float2 f0 = __half22float2(p0), f1 = __half22float2(p1);
    uint2 r;
    r.x = f2_to_bf2(f0.x, f0.y);
    r.y = f2_to_bf2(f1.x, f1.y);
    return r;
}

template <typename T>
__global__ void __launch_bounds__(256, 2)
k_gemm_mma(const T* __restrict__ A, const float* __restrict__ W,
           const float* __restrict__ dinv, uint8_t* __restrict__ H8,
           float esc, int M) {
    extern __shared__ bf16_t smh[];
    bf16_t* As = smh;              // 128 x SLD
    bf16_t* Ws = smh + 128 * SLD;  // 128 x SLD

    const int tid = threadIdx.x;
    const int block_row = blockIdx.x * 128;

    #pragma unroll 4
    for (int i = tid; i < 4096; i += 256) {
        int r = i >> 5, c4 = i & 31;
        *(uint2*)(Ws + r * SLD + c4 * 4) = load_row4(W + r * F, c4);
    }
    #pragma unroll 4
    for (int i = tid; i < 4096; i += 256) {
        int r = i >> 5, c4 = i & 31;
        int gr = block_row + r;
        uint2 u = make_uint2(0u, 0u);
        if (gr < M) u = load_row4(A + (size_t)gr * F, c4);
        *(uint2*)(As + r * SLD + c4 * 4) = u;
    }
    __syncthreads();

    const int wid = tid >> 5, lane = tid & 31;
    const int wm = (wid & 3) * 32;
    const int wn = (wid >> 2) * 64;

    float acc[2][8][4];
    #pragma unroll
    for (int mt = 0; mt < 2; mt++)
        #pragma unroll
        for (int nt = 0; nt < 8; nt++)
            #pragma unroll
            for (int q = 0; q < 4; q++) acc[mt][nt][q] = 0.f;

    const uint32_t As_b = smem_u32(As);
    const uint32_t Ws_b = smem_u32(Ws);
    const int lrow = lane & 15;
    const int lcol = (lane >> 4) * 8;

    #pragma unroll
    for (int kb = 0; kb < 8; kb++) {
        uint32_t a[2][4];
        #pragma unroll
        for (int mt = 0; mt < 2; mt++) {
            int row = wm + mt * 16 + lrow;
            int col = kb * 16 + lcol;
            ldsm_x4(a[mt], As_b + (row * SLD + col) * 2);
        }
        uint32_t b[8][2];
        #pragma unroll
        for (int np = 0; np < 4; np++) {
            int krow = kb * 16 + lrow;
            int ncol = wn + np * 16 + lcol;
            uint32_t r[4];
            ldsm_x4_t(r, Ws_b + (krow * SLD + ncol) * 2);
            b[np * 2][0] = r[0]; b[np * 2][1] = r[1];
            b[np * 2 + 1][0] = r[2]; b[np * 2 + 1][1] = r[3];
        }
        #pragma unroll
        for (int mt = 0; mt < 2; mt++)
            #pragma unroll
            for (int nt = 0; nt < 8; nt++)
                mma_bf16(acc[mt][nt], a[mt], b[nt][0], b[nt][1]);
    }

    #pragma unroll
    for (int mt = 0; mt < 2; mt++) {
        int r0 = block_row + wm + mt * 16 + (lane >> 2);
        int r1 = r0 + 8;
        float d0 = __ldg(dinv + min(r0, M - 1)) * esc;
        float d1 = __ldg(dinv + min(r1, M - 1)) * esc;
        #pragma unroll
        for (int nt = 0; nt < 8; nt++) {
            int col = wn + nt * 8 + (lane & 3) * 2;
            if (r0 < M)
                *(uint16_t*)(H8 + (size_t)r0 * F + col) =
                    f2_to_e4m3x2(acc[mt][nt][0] * d0, acc[mt][nt][1] * d0);
            if (r1 < M)
                *(uint16_t*)(H8 + (size_t)r1 * F + col) =
                    f2_to_e4m3x2(acc[mt][nt][2] * d1, acc[mt][nt][3] * d1);
        }
    }
}

// ---------------------------------------------------------------------------
// Gather aggregation, LDG.64 / 2-edges-per-load layout:
//   lane = 16*e + q (e in {0,1}, q in 0..15); lane covers bytes [8q, 8q+8) of
//   its edge-group's rows. One warp LDG.64 = 2 edge rows. 8 loads in flight
//   = 16 edges. Cross-group combine: shfl_xor(16) per feature at the end.
//   a[c] = (dc/16) * ( sum_{r in N(c)} H'[r] + H'[c] ) + bias
// ---------------------------------------------------------------------------
#define NPW 4

// accumulate 4 half2-quads (one LDG.64 worth) into 8 fp32 accumulators
__device__ __forceinline__ void h2x4_flush(const H2x4& v, float* accF) {
    float2 f;
    f = __half22float2(v.a); accF[0] += f.x; accF[1] += f.y;
    f = __half22float2(v.b); accF[2] += f.x; accF[3] += f.y;
    f = __half22float2(v.c); accF[4] += f.x; accF[5] += f.y;
    f = __half22float2(v.d); accF[6] += f.x; accF[7] += f.y;
}

template <bool FUSE_HEAD>
__global__ void __launch_bounds__(256)
k_agg(const int* __restrict__ start, const int* __restrict__ srow,
      const float* __restrict__ dinv, const uint8_t* __restrict__ H8,
      const float* __restrict__ bias,
      const float* __restrict__ Wl, const float* __restrict__ bl,
      uint8_t* __restrict__ hout8, float* __restrict__ fout, int n) {
    const int lane = threadIdx.x & 31;
    const int q = lane & 15;          // byte-octet within row
    const int e = lane >> 4;          // edge group (0 or 1)
    const int warp = (blockIdx.x * blockDim.x + threadIdx.x) >> 5;
    int c0 = warp * NPW;
    if (c0 >= n) return;
    int c_end = min(c0 + NPW, n);

    // per-lane bias/head slices: features [8q, 8q+8)
    float bvf[8], wlf[8];
    {
        float4 b0 = __ldg((const float4*)bias + q * 2);
        float4 b1 = __ldg((const float4*)bias + q * 2 + 1);
        bvf[0]=b0.x; bvf[1]=b0.y; bvf[2]=b0.z; bvf[3]=b0.w;
        bvf[4]=b1.x; bvf[5]=b1.y; bvf[6]=b1.z; bvf[7]=b1.w;
        if (FUSE_HEAD) {
            float4 w0 = __ldg((const float4*)Wl + q * 2);
            float4 w1 = __ldg((const float4*)Wl + q * 2 + 1);
            wlf[0]=w0.x; wlf[1]=w0.y; wlf[2]=w0.z; wlf[3]=w0.w;
            wlf[4]=w1.x; wlf[5]=w1.y; wlf[6]=w1.z; wlf[7]=w1.w;
        }
    }
    float blv = FUSE_HEAD ? __ldg(bl) : 0.f;

    for (int c = c0; c < c_end; c++) {
        int beg = __ldg(start + c);
        int end = __ldg(start + c + 1);
        float dc = __ldg(dinv + c) * (1.0f / FP8_SCALE);

        float accF[8];
        // self term: only group 0 (avoid double count after combine)
        if (e == 0) {
            uint2 su = __ldg((const uint2*)(H8 + (size_t)c * F) + q);
            H2x4 v = fp8x8_to_h2(su);
            float2 f;
            f = __half22float2(v.a); accF[0] = f.x; accF[1] = f.y;
            f = __half22float2(v.b); accF[2] = f.x; accF[3] = f.y;
            f = __half22float2(v.c); accF[4] = f.x; accF[5] = f.y;
            f = __half22float2(v.d); accF[6] = f.x; accF[7] = f.y;
        } else {
            #pragma unroll
            for (int i = 0; i < 8; i++) accF[i] = 0.f;
        }

        for (int i = beg; i < end; i += 32) {
            int idx = i + lane;
            int rr = __ldg(srow + (idx < end ? idx : end - 1));
            int cnt = min(end - i, 32);
            int j = 0;
            // 16 edges per step: 8 LDG.64 in flight
            for (; j + 16 <= cnt; j += 16) {
                int r0 = __shfl_sync(0xFFFFFFFFu, rr, j + 0  + e);
                int r1 = __shfl_sync(0xFFFFFFFFu, rr, j + 2  + e);
                int r2 = __shfl_sync(0xFFFFFFFFu, rr, j + 4  + e);
                int r3 = __shfl_sync(0xFFFFFFFFu, rr, j + 6  + e);
                int r4 = __shfl_sync(0xFFFFFFFFu, rr, j + 8  + e);
                int r5 = __shfl_sync(0xFFFFFFFFu, rr, j + 10 + e);
                int r6 = __shfl_sync(0xFFFFFFFFu, rr, j + 12 + e);
                int r7 = __shfl_sync(0xFFFFFFFFu, rr, j + 14 + e);
                uint2 u0 = __ldg((const uint2*)(H8 + (size_t)r0 * F) + q);
                uint2 u1 = __ldg((const uint2*)(H8 + (size_t)r1 * F) + q);
                uint2 u2 = __ldg((const uint2*)(H8 + (size_t)r2 * F) + q);
                uint2 u3 = __ldg((const uint2*)(H8 + (size_t)r3 * F) + q);
                uint2 u4 = __ldg((const uint2*)(H8 + (size_t)r4 * F) + q);
                uint2 u5 = __ldg((const uint2*)(H8 + (size_t)r5 * F) + q);
                uint2 u6 = __ldg((const uint2*)(H8 + (size_t)r6 * F) + q);
                uint2 u7 = __ldg((const uint2*)(H8 + (size_t)r7 * F) + q);
                H2x4 v0 = fp8x8_to_h2(u0), v1 = fp8x8_to_h2(u1);
                H2x4 v2 = fp8x8_to_h2(u2), v3 = fp8x8_to_h2(u3);
                H2x4 v4 = fp8x8_to_h2(u4), v5 = fp8x8_to_h2(u5);
                H2x4 v6 = fp8x8_to_h2(u6), v7 = fp8x8_to_h2(u7);
                H2x4 s;
                s.a = __hadd2(__hadd2(__hadd2(v0.a, v1.a), __hadd2(v2.a, v3.a)),
                              __hadd2(__hadd2(v4.a, v5.a), __hadd2(v6.a, v7.a)));
                s.b = __hadd2(__hadd2(__hadd2(v0.b, v1.b), __hadd2(v2.b, v3.b)),
                              __hadd2(__hadd2(v4.b, v5.b), __hadd2(v6.b, v7.b)));
                s.c = __hadd2(__hadd2(__hadd2(v0.c, v1.c), __hadd2(v2.c, v3.c)),
                              __hadd2(__hadd2(v4.c, v5.c), __hadd2(v6.c, v7.c)));
                s.d = __hadd2(__hadd2(__hadd2(v0.d, v1.d), __hadd2(v2.d, v3.d)),
                              __hadd2(__hadd2(v4.d, v5.d), __hadd2(v6.d, v7.d)));
                h2x4_flush(s, accF);
            }
            // 2 edges per step
            for (; j + 2 <= cnt; j += 2) {
                int r0 = __shfl_sync(0xFFFFFFFFu, rr, j + e);
                uint2 u0 = __ldg((const uint2*)(H8 + (size_t)r0 * F) + q);
                H2x4 v = fp8x8_to_h2(u0);
                h2x4_flush(v, accF);
            }
            // single leftover edge: group 0 only
            if (j < cnt) {
                int r0 = __shfl_sync(0xFFFFFFFFu, rr, j);
                if (e == 0) {
                    uint2 u0 = __ldg((const uint2*)(H8 + (size_t)r0 * F) + q);
                    H2x4 v = fp8x8_to_h2(u0);
                    h2x4_flush(v, accF);
                }
            }
        }

        // combine edge groups: lanes l and l^16 hold same q, different edges
        #pragma unroll
        for (int i = 0; i < 8; i++)
            accF[i] += __shfl_xor_sync(0xFFFFFFFFu, accF[i], 16);

        if (!FUSE_HEAD) {
            float o[8];
            #pragma unroll
            for (int i = 0; i < 8; i++)
                o[i] = fmaxf(fmaf(dc, accF[i], bvf[i]), 0.f) * FP8_SCALE;
            uint32_t p01 = (uint32_t)f2_to_e4m3x2(o[0], o[1]) |
                           ((uint32_t)f2_to_e4m3x2(o[2], o[3]) << 16);
            uint32_t p23 = (uint32_t)f2_to_e4m3x2(o[4], o[5]) |
                           ((uint32_t)f2_to_e4m3x2(o[6], o[7]) << 16);
            if (e == 0)
                *((uint2*)(hout8 + (size_t)c * F) + q) = make_uint2(p01, p23);
        } else {
            float s = 0.f;
            #pragma unroll
            for (int i = 0; i < 8; i++)
                s += fmaxf(fmaf(dc, accF[i], bvf[i]), 0.f) * wlf[i];
            // reduce over q (16 lanes); lanes and their ^16 twins are duplicates
            #pragma unroll
            for (int off = 8; off; off >>= 1)
                s += __shfl_xor_sync(0xFFFFFFFFu, s, off);
            if (lane == 0) {
                float z = s + blv;
                fout[c] = 1.0f / (1.0f + expf(-z));
            }
        }
    }
}

// ---------------------------------------------------------------------------
extern "C" void kernel_launch(void* const* d_in, const int* in_sizes, int n_in,
                              void* d_out, int out_size) {
    const float* x  = (const float*)d_in[0];
    const int*   ei = (const int*)  d_in[1];
    const float* W1 = (const float*)d_in[2];
    const float* b1 = (const float*)d_in[3];
    const float* W2 = (const float*)d_in[4];
    const float* b2 = (const float*)d_in[5];
    const float* Wl = (const float*)d_in[6];
    const float* bl = (const float*)d_in[7];

    int n = in_sizes[0] / F;
    int E = in_sizes[1] / 2;
    const int* rowp = ei;
    const int* colp = ei + E;

    int *cnt, *start, *cursor, *bsum, *boff, *srow;
    float *dinv;
    uint8_t *h8, *a8;
    cudaGetSymbolAddress((void**)&cnt,    g_cnt);
    cudaGetSymbolAddress((void**)&start,  g_start);
    cudaGetSymbolAddress((void**)&cursor, g_cursor);
    cudaGetSymbolAddress((void**)&bsum,   g_bsum);
    cudaGetSymbolAddress((void**)&boff,   g_boff);
    cudaGetSymbolAddress((void**)&srow,   g_srow);
    cudaGetSymbolAddress((void**)&dinv,   g_dinv);
    cudaGetSymbolAddress((void**)&h8,     g_h8);
    cudaGetSymbolAddress((void**)&a8,     g_a8);

    const size_t gemm_smem = (size_t)(2 * 128 * SLD) * sizeof(bf16_t);
    cudaFuncSetAttribute((const void*)k_gemm_mma<float>,
                         cudaFuncAttributeMaxDynamicSharedMemorySize, (int)gemm_smem);
    cudaFuncSetAttribute((const void*)k_gemm_mma<uint8_t>,
                         cudaFuncAttributeMaxDynamicSharedMemorySize, (int)gemm_smem);

    // Side stream + events for overlapping the sort chain with GEMM1.
    static cudaStream_t s2 = nullptr;
    static cudaEvent_t evA = nullptr, evB = nullptr;
    static int init_tried = 0;
    if (!init_tried) {
        init_tried = 1;
        if (cudaStreamCreateWithFlags(&s2, cudaStreamNonBlocking) != cudaSuccess) s2 = nullptr;
        if (cudaEventCreateWithFlags(&evA, cudaEventDisableTiming) != cudaSuccess) evA = nullptr;
        if (cudaEventCreateWithFlags(&evB, cudaEventDisableTiming) != cudaSuccess) evB = nullptr;
    }
    bool par = (s2 != nullptr) && (evA != nullptr) && (evB != nullptr);

    int nb = (n + SCAN_BLK - 1) / SCAN_BLK;
    int gemm_grid = (n + 127) / 128;
    int agg_grid  = ((n + NPW - 1) / NPW * 32 + 255) / 256;

    // --- degree + dinv (cnt zeroed via memset node) ---
    cudaMemsetAsync(cnt, 0, (size_t)n * sizeof(int), 0);
    k_hist<<<(E + 255) / 256, 256>>>(colp, cnt, E);
    k_dinv<<<(n + 255) / 256, 256>>>(cnt, dinv, n);

    if (par) {
        cudaEventRecord(evA, 0);
        cudaStreamWaitEvent(s2, evA, 0);
        k_blocksum<<<nb, 256, 0, s2>>>(cnt, bsum, n);
        k_gemm_mma<float><<<gemm_grid, 256, gemm_smem>>>(x, W1, dinv, h8, FP8_SCALE, n);
        k_scanbsum  <<<1, 256, 0, s2>>>(bsum, boff, start, nb, n);
        k_writestart<<<nb, 256, 0, s2>>>(cnt, boff, start, cursor, n);
        k_scatter   <<<(E + 255) / 256, 256, 0, s2>>>(rowp, colp, cursor, srow, E);
        cudaEventRecord(evB, s2);
        cudaStreamWaitEvent(0, evB, 0);
    } else {
        k_blocksum  <<<nb, 256>>>(cnt, bsum, n);
        k_gemm_mma<float><<<gemm_grid, 256, gemm_smem>>>(x, W1, dinv, h8, FP8_SCALE, n);
        k_scanbsum  <<<1, 256>>>(bsum, boff, start, nb, n);
        k_writestart<<<nb, 256>>>(cnt, boff, start, cursor, n);
        k_scatter   <<<(E + 255) / 256, 256>>>(rowp, colp, cursor, srow, E);
    }

    // --- layer 1 agg (fp8 gather, LDG.64 layout) -> fp8 a8 (x16) ---
    k_agg<false><<<agg_grid, 256>>>(start, srow, dinv, h8, b1, nullptr, nullptr, a8, nullptr, n);

    // --- layer 2: A carries x16 -> esc = 1.0 keeps H8 = 16*dinv*(a@W2) ---
    k_gemm_mma<uint8_t><<<gemm_grid, 256, gemm_smem>>>(a8, W2, dinv, h8, 1.0f, n);
    k_agg<true><<<agg_grid, 256>>>(start, srow, dinv, h8, b2, Wl, bl, nullptr, (float*)d_out, n);
}

// round 12
// speedup vs baseline: 1.2398x; 1.0696x over previous
#include <cuda_runtime.h>
#include <cuda_fp16.h>
#include <cstdint>

#define NMAX 100000
#define EMAX 3200000
#define F 128
#define FP8_SCALE 16.0f

typedef unsigned short bf16_t;

// Scratch (device globals — no allocation allowed)
__device__ int     g_cnt   [NMAX];
__device__ int     g_start [NMAX + 1];
__device__ int     g_cursor[NMAX];
__device__ int     g_bsum  [256];
__device__ int     g_boff  [256];
__device__ int     g_srow  [EMAX];              // edge row-ids sorted by col
__device__ float   g_dinv  [NMAX];
__device__ uint8_t g_h8    [(size_t)NMAX * F];  // GEMM out (both layers): fp8, prescaled dinv*16
__device__ uint8_t g_a8    [(size_t)NMAX * F];  // layer-1 agg output: fp8, relu'd, *16

// ---------------------------------------------------------------------------
// numeric helpers
// ---------------------------------------------------------------------------
__device__ __forceinline__ uint32_t f2_to_bf2(float lo, float hi) {
    uint32_t r;
    asm("cvt.rn.bf16x2.f32 %0, %1, %2;" : "=r"(r) : "f"(hi), "f"(lo));
    return r;
}

__device__ __forceinline__ uint16_t f2_to_e4m3x2(float lo, float hi) {
    uint16_t r;
    asm("cvt.rn.satfinite.e4m3x2.f32 %0, %1, %2;" : "=h"(r) : "f"(hi), "f"(lo));
    return r;
}

__device__ __forceinline__ __half2 e4m3x2_to_h2(uint16_t v) {
    uint32_t r;
    asm("cvt.rn.f16x2.e4m3x2 %0, %1;" : "=r"(r) : "h"(v));
    return *(__half2*)&r;
}

__device__ __forceinline__ void fp8x4_to_h2(uint32_t u, __half2& p0, __half2& p1) {
    p0 = e4m3x2_to_h2((uint16_t)(u & 0xFFFFu));
    p1 = e4m3x2_to_h2((uint16_t)(u >> 16));
}

// ---------------------------------------------------------------------------
// degree histogram / dinv
// ---------------------------------------------------------------------------
__global__ void k_hist(const int* __restrict__ col, int* __restrict__ cnt, int E) {
    int i = blockIdx.x * blockDim.x + threadIdx.x;
    if (i < E) atomicAdd(&cnt[col[i]], 1);
}

__global__ void k_dinv(const int* __restrict__ cnt, float* __restrict__ dinv, int n) {
    int i = blockIdx.x * blockDim.x + threadIdx.x;
    if (i < n) dinv[i] = rsqrtf((float)(cnt[i] + 1));  // +1 self-loop
}

// ---------------------------------------------------------------------------
// Counting sort of edges by col
// ---------------------------------------------------------------------------
#define SCAN_BLK 1024

__global__ void k_blocksum(const int* __restrict__ cnt, int* __restrict__ bsum, int n) {
    __shared__ int sm[256];
    int t = threadIdx.x, b = blockIdx.x;
    int base = b * SCAN_BLK;
    int s = 0;
    #pragma unroll
    for (int k = 0; k < 4; k++) {
        int i = base + t * 4 + k;
        if (i < n) s += cnt[i];
    }
    sm[t] = s; __syncthreads();
    for (int off = 128; off > 0; off >>= 1) {
        if (t < off) sm[t] += sm[t + off];
        __syncthreads();
    }
    if (t == 0) bsum[b] = sm[0];
}

__global__ void k_scanbsum(const int* __restrict__ bsum, int* __restrict__ boff,
                           int* __restrict__ start, int nb, int n) {
    __shared__ int sm[256];
    int t = threadIdx.x;
    int v = (t < nb) ? bsum[t] : 0;
    sm[t] = v; __syncthreads();
    #pragma unroll
    for (int off = 1; off < 256; off <<= 1) {
        int x = 0;
        if (t >= off) x = sm[t - off];
        __syncthreads();
        sm[t] += x;
        __syncthreads();
    }
    if (t < nb) boff[t] = sm[t] - v;
    if (t == 255) start[n] = sm[255];
}

__global__ void k_writestart(const int* __restrict__ cnt, const int* __restrict__ boff,
                             int* __restrict__ start, int* __restrict__ cursor, int n) {
    __shared__ int sm[256];
    int t = threadIdx.x, b = blockIdx.x;
    int base = b * SCAN_BLK + t * 4;
    int c[4]; int s = 0;
    #pragma unroll
    for (int k = 0; k < 4; k++) {
        c[k] = (base + k < n) ? cnt[base + k] : 0;
        s += c[k];
    }
    sm[t] = s; __syncthreads();
    #pragma unroll
    for (int off = 1; off < 256; off <<= 1) {
        int x = 0;
        if (t >= off) x = sm[t - off];
        __syncthreads();
        sm[t] += x;
        __syncthreads();
    }
    int excl = boff[b] + sm[t] - s;
    #pragma unroll
    for (int k = 0; k < 4; k++) {
        int i = base + k;
        if (i < n) { start[i] = excl; cursor[i] = excl; }
        excl += c[k];
    }
}

__global__ void k_scatter(const int* __restrict__ row, const int* __restrict__ col,
                          int* __restrict__ cursor, int* __restrict__ srow, int E) {
    int i = blockIdx.x * blockDim.x + threadIdx.x;
    if (i >= E) return;
    int c = col[i];
    int pos = atomicAdd(&cursor[c], 1);
    srow[pos] = row[i];
}

// ---------------------------------------------------------------------------
// Tensor-core GEMM (bf16 mma): H8(fp8) = (A @ W) * dinv[row] * esc
// A may be fp32 (layer 1) or fp8 (layer 2; values carry x16 already, esc=1).
// CTA = 128x128 tile, 512 threads (16 warps, warp tile 32x32) -> 50% occ.
// ---------------------------------------------------------------------------
#define SLD 136

__device__ __forceinline__ uint32_t smem_u32(const void* p) {
    return (uint32_t)__cvta_generic_to_shared(p);
}

__device__ __forceinline__ void ldsm_x4(uint32_t* r, uint32_t addr) {
    asm volatile("ldmatrix.sync.aligned.m8n8.x4.shared.b16 {%0,%1,%2,%3}, [%4];"
                 : "=r"(r[0]), "=r"(r[1]), "=r"(r[2]), "=r"(r[3]) : "r"(addr));
}

__device__ __forceinline__ void ldsm_x4_t(uint32_t* r, uint32_t addr) {
    asm volatile("ldmatrix.sync.aligned.m8n8.x4.trans.shared.b16 {%0,%1,%2,%3}, [%4];"
                 : "=r"(r[0]), "=r"(r[1]), "=r"(r[2]), "=r"(r[3]) : "r"(addr));
}

__device__ __forceinline__ void mma_bf16(float* c, const uint32_t* a,
                                         uint32_t b0, uint32_t b1) {
    asm volatile(
        "mma.sync.aligned.m16n8k16.row.col.f32.bf16.bf16.f32 "
        "{%0,%1,%2,%3}, {%4,%5,%6,%7}, {%8,%9}, {%0,%1,%2,%3};"
        : "+f"(c[0]), "+f"(c[1]), "+f"(c[2]), "+f"(c[3])
        : "r"(a[0]), "r"(a[1]), "r"(a[2]), "r"(a[3]), "r"(b0), "r"(b1));
}

__device__ __forceinline__ uint2 load_row4(const float* base, int c4) {
    float4 v = __ldg((const float4*)base + c4);
    uint2 u;
    u.x = f2_to_bf2(v.x, v.y);
    u.y = f2_to_bf2(v.z, v.w);
    return u;
}

// fp8 row load: 4 e4m3 -> bf16x2 pair (exact: e4m3 mantissa fits bf16)
__device__ __forceinline__ uint2 load_row4(const uint8_t* base, int c4) {
    uint32_t u = __ldg((const uint32_t*)base + c4);
    __half2 p0, p1; fp8x4_to_h2(u, p0, p1);
    float2 f0 = __half22float2(p0), f1 = __half22float2(p1);
    uint2 r;
    r.x = f2_to_bf2(f0.x, f0.y);
    r.y = f2_to_bf2(f1.x, f1.y);
    return r;
}

template <typename T>
__global__ void __launch_bounds__(512, 2)
k_gemm_mma(const T* __restrict__ A, const float* __restrict__ W,
           const float* __restrict__ dinv, uint8_t* __restrict__ H8,
           float esc, int M) {
    extern __shared__ bf16_t smh[];
    bf16_t* As = smh;              // 128 x SLD
    bf16_t* Ws = smh + 128 * SLD;  // 128 x SLD

    const int tid = threadIdx.x;
    const int block_row = blockIdx.x * 128;

    #pragma unroll
    for (int i = tid; i < 4096; i += 512) {
        int r = i >> 5, c4 = i & 31;
        *(uint2*)(Ws + r * SLD + c4 * 4) = load_row4(W + r * F, c4);
    }
    #pragma unroll
    for (int i = tid; i < 4096; i += 512) {
        int r = i >> 5, c4 = i & 31;
        int gr = block_row + r;
        uint2 u = make_uint2(0u, 0u);
        if (gr < M) u = load_row4(A + (size_t)gr * F, c4);
        *(uint2*)(As + r * SLD + c4 * 4) = u;
    }
    __syncthreads();

    const int wid = tid >> 5, lane = tid & 31;
    const int wm = (wid & 3) * 32;   // 4 warp-rows
    const int wn = (wid >> 2) * 32;  // 4 warp-cols

    float acc[2][4][4];
    #pragma unroll
    for (int mt = 0; mt < 2; mt++)
        #pragma unroll
        for (int nt = 0; nt < 4; nt++)
            #pragma unroll
            for (int q = 0; q < 4; q++) acc[mt][nt][q] = 0.f;

    const uint32_t As_b = smem_u32(As);
    const uint32_t Ws_b = smem_u32(Ws);
    const int lrow = lane & 15;
    const int lcol = (lane >> 4) * 8;

    #pragma unroll
    for (int kb = 0; kb < 8; kb++) {
        uint32_t a[2][4];
        #pragma unroll
        for (int mt = 0; mt < 2; mt++) {
            int row = wm + mt * 16 + lrow;
            int col = kb * 16 + lcol;
            ldsm_x4(a[mt], As_b + (row * SLD + col) * 2);
        }
        uint32_t b[4][2];
        #pragma unroll
        for (int np = 0; np < 2; np++) {
            int krow = kb * 16 + lrow;
            int ncol = wn + np * 16 + lcol;
            uint32_t r[4];
            ldsm_x4_t(r, Ws_b + (krow * SLD + ncol) * 2);
            b[np * 2][0] = r[0]; b[np * 2][1] = r[1];
            b[np * 2 + 1][0] = r[2]; b[np * 2 + 1][1] = r[3];
        }
        #pragma unroll
        for (int mt = 0; mt < 2; mt++)
            #pragma unroll
            for (int nt = 0; nt < 4; nt++)
                mma_bf16(acc[mt][nt], a[mt], b[nt][0], b[nt][1]);
    }

    // Epilogue: scale by dinv[row]*esc, store fp8
    #pragma unroll
    for (int mt = 0; mt < 2; mt++) {
        int r0 = block_row + wm + mt * 16 + (lane >> 2);
        int r1 = r0 + 8;
        float d0 = __ldg(dinv + min(r0, M - 1)) * esc;
        float d1 = __ldg(dinv + min(r1, M - 1)) * esc;
        #pragma unroll
        for (int nt = 0; nt < 4; nt++) {
            int col = wn + nt * 8 + (lane & 3) * 2;
            if (r0 < M)
                *(uint16_t*)(H8 + (size_t)r0 * F + col) =
                    f2_to_e4m3x2(acc[mt][nt][0] * d0, acc[mt][nt][1] * d0);
            if (r1 < M)
                *(uint16_t*)(H8 + (size_t)r1 * F + col) =
                    f2_to_e4m3x2(acc[mt][nt][2] * d1, acc[mt][nt][3] * d1);
        }
    }
}

// ---------------------------------------------------------------------------
// Gather aggregation over prescaled fp8 H' (128B rows)  [round-9 form]:
//   a[c] = (dc/16) * ( sum_{r in N(c)} H'[r] + H'[c] ) + bias
// Warp handles 4 nodes; lane = 4 features (4B load); 8 edges in flight.
// ---------------------------------------------------------------------------
#define NPW 4

__device__ __forceinline__ void tree4_acc(uint32_t u0, uint32_t u1,
                                          uint32_t u2, uint32_t u3, float4& acc) {
    __half2 a0, b0, a1, b1, a2, b2, a3, b3;
    fp8x4_to_h2(u0, a0, b0);
    fp8x4_to_h2(u1, a1, b1);
    fp8x4_to_h2(u2, a2, b2);
    fp8x4_to_h2(u3, a3, b3);
    __half2 sa = __hadd2(__hadd2(a0, a1), __hadd2(a2, a3));
    __half2 sb = __hadd2(__hadd2(b0, b1), __hadd2(b2, b3));
    float2 fa = __half22float2(sa), fb = __half22float2(sb);
    acc.x += fa.x; acc.y += fa.y; acc.z += fb.x; acc.w += fb.y;
}

template <bool FUSE_HEAD>
__global__ void __launch_bounds__(256)
k_agg(const int* __restrict__ start, const int* __restrict__ srow,
      const float* __restrict__ dinv, const uint8_t* __restrict__ H8,
      const float* __restrict__ bias,
      const float* __restrict__ Wl, const float* __restrict__ bl,
      uint8_t* __restrict__ hout8, float* __restrict__ fout, int n) {
    const int lane = threadIdx.x & 31;
    const int warp = (blockIdx.x * blockDim.x + threadIdx.x) >> 5;
    int c0 = warp * NPW;
    if (c0 >= n) return;
    int c_end = min(c0 + NPW, n);

    float4 bv = __ldg((const float4*)bias + lane);
    float4 wv = make_float4(0.f, 0.f, 0.f, 0.f);
    float blv = 0.f;
    if (FUSE_HEAD) { wv = __ldg((const float4*)Wl + lane); blv = __ldg(bl); }

    for (int c = c0; c < c_end; c++) {
        int beg = __ldg(start + c);
        int end = __ldg(start + c + 1);
        float dc = __ldg(dinv + c) * (1.0f / FP8_SCALE);

        uint32_t su = __ldg((const uint32_t*)(H8 + (size_t)c * F) + lane);
        __half2 spa, spb; fp8x4_to_h2(su, spa, spb);
        float2 sfa = __half22float2(spa), sfb = __half22float2(spb);
        float4 acc = make_float4(sfa.x, sfa.y, sfb.x, sfb.y);

        for (int i = beg; i < end; i += 32) {
            int idx = i + lane;
            int rr = __ldg(srow + (idx < end ? idx : end - 1));
            int cnt = min(end - i, 32);
            int j = 0;
            for (; j + 8 <= cnt; j += 8) {
                int r0 = __shfl_sync(0xFFFFFFFFu, rr, j);
                int r1 = __shfl_sync(0xFFFFFFFFu, rr, j + 1);
                int r2 = __shfl_sync(0xFFFFFFFFu, rr, j + 2);
                int r3 = __shfl_sync(0xFFFFFFFFu, rr, j + 3);
                int r4 = __shfl_sync(0xFFFFFFFFu, rr, j + 4);
                int r5 = __shfl_sync(0xFFFFFFFFu, rr, j + 5);
                int r6 = __shfl_sync(0xFFFFFFFFu, rr, j + 6);
                int r7 = __shfl_sync(0xFFFFFFFFu, rr, j + 7);
                uint32_t u0 = __ldg((const uint32_t*)(H8 + (size_t)r0 * F) + lane);
                uint32_t u1 = __ldg((const uint32_t*)(H8 + (size_t)r1 * F) + lane);
                uint32_t u2 = __ldg((const uint32_t*)(H8 + (size_t)r2 * F) + lane);
                uint32_t u3 = __ldg((const uint32_t*)(H8 + (size_t)r3 * F) + lane);
                uint32_t u4 = __ldg((const uint32_t*)(H8 + (size_t)r4 * F) + lane);
                uint32_t u5 = __ldg((const uint32_t*)(H8 + (size_t)r5 * F) + lane);
                uint32_t u6 = __ldg((const uint32_t*)(H8 + (size_t)r6 * F) + lane);
                uint32_t u7 = __ldg((const uint32_t*)(H8 + (size_t)r7 * F) + lane);
                tree4_acc(u0, u1, u2, u3, acc);
                tree4_acc(u4, u5, u6, u7, acc);
            }
            for (; j + 4 <= cnt; j += 4) {
                int r0 = __shfl_sync(0xFFFFFFFFu, rr, j);
                int r1 = __shfl_sync(0xFFFFFFFFu, rr, j + 1);
                int r2 = __shfl_sync(0xFFFFFFFFu, rr, j + 2);
                int r3 = __shfl_sync(0xFFFFFFFFu, rr, j + 3);
                uint32_t u0 = __ldg((const uint32_t*)(H8 + (size_t)r0 * F) + lane);
                uint32_t u1 = __ldg((const uint32_t*)(H8 + (size_t)r1 * F) + lane);
                uint32_t u2 = __ldg((const uint32_t*)(H8 + (size_t)r2 * F) + lane);
                uint32_t u3 = __ldg((const uint32_t*)(H8 + (size_t)r3 * F) + lane);
                tree4_acc(u0, u1, u2, u3, acc);
            }
            for (; j < cnt; j++) {
                int r0 = __shfl_sync(0xFFFFFFFFu, rr, j);
                uint32_t u0 = __ldg((const uint32_t*)(H8 + (size_t)r0 * F) + lane);
                __half2 pa, pb; fp8x4_to_h2(u0, pa, pb);
                float2 fa = __half22float2(pa), fb = __half22float2(pb);
                acc.x += fa.x; acc.y += fa.y; acc.z += fb.x; acc.w += fb.y;
            }
        }

        float4 o = make_float4(fmaf(dc, acc.x, bv.x), fmaf(dc, acc.y, bv.y),
                               fmaf(dc, acc.z, bv.z), fmaf(dc, acc.w, bv.w));

        if (!FUSE_HEAD) {
            o.x = fmaxf(o.x, 0.f) * FP8_SCALE; o.y = fmaxf(o.y, 0.f) * FP8_SCALE;
            o.z = fmaxf(o.z, 0.f) * FP8_SCALE; o.w = fmaxf(o.w, 0.f) * FP8_SCALE;
            uint32_t lo = f2_to_e4m3x2(o.x, o.y);
            uint32_t hi = f2_to_e4m3x2(o.z, o.w);
            *((uint32_t*)(hout8 + (size_t)c * F) + lane) = lo | (hi << 16);
        } else {
            float s = fmaxf(o.x, 0.f) * wv.x + fmaxf(o.y, 0.f) * wv.y +
                      fmaxf(o.z, 0.f) * wv.z + fmaxf(o.w, 0.f) * wv.w;
            #pragma unroll
            for (int off = 16; off; off >>= 1) s += __shfl_xor_sync(0xFFFFFFFFu, s, off);
            if (lane == 0) {
                float z = s + blv;
                fout[c] = 1.0f / (1.0f + expf(-z));
            }
        }
    }
}

// ---------------------------------------------------------------------------
extern "C" void kernel_launch(void* const* d_in, const int* in_sizes, int n_in,
                              void* d_out, int out_size) {
    const float* x  = (const float*)d_in[0];
    const int*   ei = (const int*)  d_in[1];
    const float* W1 = (const float*)d_in[2];
    const float* b1 = (const float*)d_in[3];
    const float* W2 = (const float*)d_in[4];
    const float* b2 = (const float*)d_in[5];
    const float* Wl = (const float*)d_in[6];
    const float* bl = (const float*)d_in[7];

    int n = in_sizes[0] / F;
    int E = in_sizes[1] / 2;
    const int* rowp = ei;
    const int* colp = ei + E;

    int *cnt, *start, *cursor, *bsum, *boff, *srow;
    float *dinv;
    uint8_t *h8, *a8;
    cudaGetSymbolAddress((void**)&cnt,    g_cnt);
    cudaGetSymbolAddress((void**)&start,  g_start);
    cudaGetSymbolAddress((void**)&cursor, g_cursor);
    cudaGetSymbolAddress((void**)&bsum,   g_bsum);
    cudaGetSymbolAddress((void**)&boff,   g_boff);
    cudaGetSymbolAddress((void**)&srow,   g_srow);
    cudaGetSymbolAddress((void**)&dinv,   g_dinv);
    cudaGetSymbolAddress((void**)&h8,     g_h8);
    cudaGetSymbolAddress((void**)&a8,     g_a8);

    const size_t gemm_smem = (size_t)(2 * 128 * SLD) * sizeof(bf16_t);
    cudaFuncSetAttribute((const void*)k_gemm_mma<float>,
                         cudaFuncAttributeMaxDynamicSharedMemorySize, (int)gemm_smem);
    cudaFuncSetAttribute((const void*)k_gemm_mma<uint8_t>,
                         cudaFuncAttributeMaxDynamicSharedMemorySize, (int)gemm_smem);

    // Side stream + events for overlapping the sort chain with GEMM1.
    static cudaStream_t s2 = nullptr;
    static cudaEvent_t evA = nullptr, evB = nullptr;
    static int init_tried = 0;
    if (!init_tried) {
        init_tried = 1;
        if (cudaStreamCreateWithFlags(&s2, cudaStreamNonBlocking) != cudaSuccess) s2 = nullptr;
        if (cudaEventCreateWithFlags(&evA, cudaEventDisableTiming) != cudaSuccess) evA = nullptr;
        if (cudaEventCreateWithFlags(&evB, cudaEventDisableTiming) != cudaSuccess) evB = nullptr;
    }
    bool par = (s2 != nullptr) && (evA != nullptr) && (evB != nullptr);

    int nb = (n + SCAN_BLK - 1) / SCAN_BLK;
    int gemm_grid = (n + 127) / 128;
    int agg_grid  = ((n + NPW - 1) / NPW * 32 + 255) / 256;

    // --- degree + dinv (cnt zeroed via memset node) ---
    cudaMemsetAsync(cnt, 0, (size_t)n * sizeof(int), 0);
    k_hist<<<(E + 255) / 256, 256>>>(colp, cnt, E);
    k_dinv<<<(n + 255) / 256, 256>>>(cnt, dinv, n);

    if (par) {
        cudaEventRecord(evA, 0);
        cudaStreamWaitEvent(s2, evA, 0);
        k_blocksum<<<nb, 256, 0, s2>>>(cnt, bsum, n);
        k_gemm_mma<float><<<gemm_grid, 512, gemm_smem>>>(x, W1, dinv, h8, FP8_SCALE, n);
        k_scanbsum  <<<1, 256, 0, s2>>>(bsum, boff, start, nb, n);
        k_writestart<<<nb, 256, 0, s2>>>(cnt, boff, start, cursor, n);
        k_scatter   <<<(E + 255) / 256, 256, 0, s2>>>(rowp, colp, cursor, srow, E);
        cudaEventRecord(evB, s2);
        cudaStreamWaitEvent(0, evB, 0);
    } else {
        k_blocksum  <<<nb, 256>>>(cnt, bsum, n);
        k_gemm_mma<float><<<gemm_grid, 512, gemm_smem>>>(x, W1, dinv, h8, FP8_SCALE, n);
        k_scanbsum  <<<1, 256>>>(bsum, boff, start, nb, n);
        k_writestart<<<nb, 256>>>(cnt, boff, start, cursor, n);
        k_scatter   <<<(E + 255) / 256, 256>>>(rowp, colp, cursor, srow, E);
    }

    // --- layer 1 agg (fp8 gather) -> fp8 a8 (x16) ---
    k_agg<false><<<agg_grid, 256>>>(start, srow, dinv, h8, b1, nullptr, nullptr, a8, nullptr, n);

    // --- layer 2: A carries x16 -> esc = 1.0 keeps H8 = 16*dinv*(a@W2) ---
    k_gemm_mma<uint8_t><<<gemm_grid, 512, gemm_smem>>>(a8, W2, dinv, h8, 1.0f, n);
    k_agg<true><<<agg_grid, 256>>>(start, srow, dinv, h8, b2, Wl, bl, nullptr, (float*)d_out, n);
}

// round 13
// speedup vs baseline: 1.2694x; 1.0238x over previous
#include <cuda_runtime.h>
#include <cuda_fp16.h>
#include <cstdint>

#define NMAX 100000
#define EMAX 3200000
#define F 128
#define FP8_SCALE 16.0f

typedef unsigned short h16_t;   // f16 storage in smem

// Scratch (device globals — no allocation allowed)
__device__ int     g_cnt   [NMAX];
__device__ int     g_start [NMAX + 1];
__device__ int     g_cursor[NMAX];
__device__ int     g_bsum  [256];
__device__ int     g_boff  [256];
__device__ int     g_srow  [EMAX];              // edge row-ids sorted by col
__device__ float   g_dinv  [NMAX];
__device__ uint8_t g_h8    [(size_t)NMAX * F];  // GEMM out (both layers): fp8, prescaled dinv*16
__device__ uint8_t g_a8    [(size_t)NMAX * F];  // layer-1 agg output: fp8, relu'd, *16

// ---------------------------------------------------------------------------
// numeric helpers
// ---------------------------------------------------------------------------
__device__ __forceinline__ uint16_t f2_to_e4m3x2(float lo, float hi) {
    uint16_t r;
    asm("cvt.rn.satfinite.e4m3x2.f32 %0, %1, %2;" : "=h"(r) : "f"(hi), "f"(lo));
    return r;
}

__device__ __forceinline__ uint32_t e4m3x2_to_f16x2(uint16_t v) {
    uint32_t r;
    asm("cvt.rn.f16x2.e4m3x2 %0, %1;" : "=r"(r) : "h"(v));
    return r;
}

// 4 packed e4m3 (u32) -> two f16x2 raw u32s (exact)
__device__ __forceinline__ void fp8x4_to_f16x2(uint32_t u, uint32_t& p0, uint32_t& p1) {
    p0 = e4m3x2_to_f16x2((uint16_t)(u & 0xFFFFu));
    p1 = e4m3x2_to_f16x2((uint16_t)(u >> 16));
}

__device__ __forceinline__ void fp8x4_to_h2(uint32_t u, __half2& p0, __half2& p1) {
    uint32_t r0, r1;
    fp8x4_to_f16x2(u, r0, r1);
    p0 = *(__half2*)&r0;
    p1 = *(__half2*)&r1;
}

__device__ __forceinline__ uint32_t pack_h2(__half2 h) { return *(uint32_t*)&h; }

// ---------------------------------------------------------------------------
// degree histogram / dinv
// ---------------------------------------------------------------------------
__global__ void k_hist(const int* __restrict__ col, int* __restrict__ cnt, int E) {
    int i = blockIdx.x * blockDim.x + threadIdx.x;
    if (i < E) atomicAdd(&cnt[col[i]], 1);
}

__global__ void k_dinv(const int* __restrict__ cnt, float* __restrict__ dinv, int n) {
    int i = blockIdx.x * blockDim.x + threadIdx.x;
    if (i < n) dinv[i] = rsqrtf((float)(cnt[i] + 1));  // +1 self-loop
}

// ---------------------------------------------------------------------------
// Counting sort of edges by col
// ---------------------------------------------------------------------------
#define SCAN_BLK 1024

__global__ void k_blocksum(const int* __restrict__ cnt, int* __restrict__ bsum, int n) {
    __shared__ int sm[256];
    int t = threadIdx.x, b = blockIdx.x;
    int base = b * SCAN_BLK;
    int s = 0;
    #pragma unroll
    for (int k = 0; k < 4; k++) {
        int i = base + t * 4 + k;
        if (i < n) s += cnt[i];
    }
    sm[t] = s; __syncthreads();
    for (int off = 128; off > 0; off >>= 1) {
        if (t < off) sm[t] += sm[t + off];
        __syncthreads();
    }
    if (t == 0) bsum[b] = sm[0];
}

__global__ void k_scanbsum(const int* __restrict__ bsum, int* __restrict__ boff,
                           int* __restrict__ start, int nb, int n) {
    __shared__ int sm[256];
    int t = threadIdx.x;
    int v = (t < nb) ? bsum[t] : 0;
    sm[t] = v; __syncthreads();
    #pragma unroll
    for (int off = 1; off < 256; off <<= 1) {
        int x = 0;
        if (t >= off) x = sm[t - off];
        __syncthreads();
        sm[t] += x;
        __syncthreads();
    }
    if (t < nb) boff[t] = sm[t] - v;
    if (t == 255) start[n] = sm[255];
}

__global__ void k_writestart(const int* __restrict__ cnt, const int* __restrict__ boff,
                             int* __restrict__ start, int* __restrict__ cursor, int n) {
    __shared__ int sm[256];
    int t = threadIdx.x, b = blockIdx.x;
    int base = b * SCAN_BLK + t * 4;
    int c[4]; int s = 0;
    #pragma unroll
    for (int k = 0; k < 4; k++) {
        c[k] = (base + k < n) ? cnt[base + k] : 0;
        s += c[k];
    }
    sm[t] = s; __syncthreads();
    #pragma unroll
    for (int off = 1; off < 256; off <<= 1) {
        int x = 0;
        if (t >= off) x = sm[t - off];
        __syncthreads();
        sm[t] += x;
        __syncthreads();
    }
    int excl = boff[b] + sm[t] - s;
    #pragma unroll
    for (int k = 0; k < 4; k++) {
        int i = base + k;
        if (i < n) { start[i] = excl; cursor[i] = excl; }
        excl += c[k];
    }
}

__global__ void k_scatter(const int* __restrict__ row, const int* __restrict__ col,
                          int* __restrict__ cursor, int* __restrict__ srow, int E) {
    int i = blockIdx.x * blockDim.x + threadIdx.x;
    if (i >= E) return;
    int c = col[i];
    int pos = atomicAdd(&cursor[c], 1);
    srow[pos] = row[i];
}

// ---------------------------------------------------------------------------
// Tensor-core GEMM (f16 mma): H8(fp8) = (A @ W) * dinv[row] * esc
// A may be fp32 (layer 1) or fp8 (layer 2; values carry x16 already, esc=1).
// CTA = 128x128 tile, 512 threads (16 warps, warp tile 32x32).
// ---------------------------------------------------------------------------
#define SLD 136

__device__ __forceinline__ uint32_t smem_u32(const void* p) {
    return (uint32_t)__cvta_generic_to_shared(p);
}

__device__ __forceinline__ void ldsm_x4(uint32_t* r, uint32_t addr) {
    asm volatile("ldmatrix.sync.aligned.m8n8.x4.shared.b16 {%0,%1,%2,%3}, [%4];"
                 : "=r"(r[0]), "=r"(r[1]), "=r"(r[2]), "=r"(r[3]) : "r"(addr));
}

__device__ __forceinline__ void ldsm_x4_t(uint32_t* r, uint32_t addr) {
    asm volatile("ldmatrix.sync.aligned.m8n8.x4.trans.shared.b16 {%0,%1,%2,%3}, [%4];"
                 : "=r"(r[0]), "=r"(r[1]), "=r"(r[2]), "=r"(r[3]) : "r"(addr));
}

__device__ __forceinline__ void mma_f16(float* c, const uint32_t* a,
                                        uint32_t b0, uint32_t b1) {
    asm volatile(
        "mma.sync.aligned.m16n8k16.row.col.f32.f16.f16.f32 "
        "{%0,%1,%2,%3}, {%4,%5,%6,%7}, {%8,%9}, {%0,%1,%2,%3};"
        : "+f"(c[0]), "+f"(c[1]), "+f"(c[2]), "+f"(c[3])
        : "r"(a[0]), "r"(a[1]), "r"(a[2]), "r"(a[3]), "r"(b0), "r"(b1));
}

// W load (cached: reused by all CTAs)
__device__ __forceinline__ uint2 load_w4(const float* base, int c4) {
    float4 v = __ldg((const float4*)base + c4);
    uint2 u;
    u.x = pack_h2(__floats2half2_rn(v.x, v.y));
    u.y = pack_h2(__floats2half2_rn(v.z, v.w));
    return u;
}

// A loads (streaming: read-once)
__device__ __forceinline__ uint2 load_a4(const float* base, int c4) {
    float4 v = __ldcs((const float4*)base + c4);
    uint2 u;
    u.x = pack_h2(__floats2half2_rn(v.x, v.y));
    u.y = pack_h2(__floats2half2_rn(v.z, v.w));
    return u;
}

__device__ __forceinline__ uint2 load_a4(const uint8_t* base, int c4) {
    uint32_t u = __ldcs((const uint32_t*)base + c4);
    uint2 r;
    fp8x4_to_f16x2(u, r.x, r.y);   // exact, 2 cvt
    return r;
}

template <typename T>
__global__ void __launch_bounds__(512, 2)
k_gemm_mma(const T* __restrict__ A, const float* __restrict__ W,
           const float* __restrict__ dinv, uint8_t* __restrict__ H8,
           float esc, int M) {
    extern __shared__ h16_t smh[];
    h16_t* As = smh;              // 128 x SLD
    h16_t* Ws = smh + 128 * SLD;  // 128 x SLD

    const int tid = threadIdx.x;
    const int block_row = blockIdx.x * 128;

    #pragma unroll
    for (int i = tid; i < 4096; i += 512) {
        int r = i >> 5, c4 = i & 31;
        *(uint2*)(Ws + r * SLD + c4 * 4) = load_w4(W + r * F, c4);
    }
    #pragma unroll
    for (int i = tid; i < 4096; i += 512) {
        int r = i >> 5, c4 = i & 31;
        int gr = block_row + r;
        uint2 u = make_uint2(0u, 0u);
        if (gr < M) u = load_a4(A + (size_t)gr * F, c4);
        *(uint2*)(As + r * SLD + c4 * 4) = u;
    }
    __syncthreads();

    const int wid = tid >> 5, lane = tid & 31;
    const int wm = (wid & 3) * 32;   // 4 warp-rows
    const int wn = (wid >> 2) * 32;  // 4 warp-cols

    float acc[2][4][4];
    #pragma unroll
    for (int mt = 0; mt < 2; mt++)
        #pragma unroll
        for (int nt = 0; nt < 4; nt++)
            #pragma unroll
            for (int q = 0; q < 4; q++) acc[mt][nt][q] = 0.f;

    const uint32_t As_b = smem_u32(As);
    const uint32_t Ws_b = smem_u32(Ws);
    const int lrow = lane & 15;
    const int lcol = (lane >> 4) * 8;

    #pragma unroll
    for (int kb = 0; kb < 8; kb++) {
        uint32_t a[2][4];
        #pragma unroll
        for (int mt = 0; mt < 2; mt++) {
            int row = wm + mt * 16 + lrow;
            int col = kb * 16 + lcol;
            ldsm_x4(a[mt], As_b + (row * SLD + col) * 2);
        }
        uint32_t b[4][2];
        #pragma unroll
        for (int np = 0; np < 2; np++) {
            int krow = kb * 16 + lrow;
            int ncol = wn + np * 16 + lcol;
            uint32_t r[4];
            ldsm_x4_t(r, Ws_b + (krow * SLD + ncol) * 2);
            b[np * 2][0] = r[0]; b[np * 2][1] = r[1];
            b[np * 2 + 1][0] = r[2]; b[np * 2 + 1][1] = r[3];
        }
        #pragma unroll
        for (int mt = 0; mt < 2; mt++)
            #pragma unroll
            for (int nt = 0; nt < 4; nt++)
                mma_f16(acc[mt][nt], a[mt], b[nt][0], b[nt][1]);
    }

    // Epilogue: scale by dinv[row]*esc, store fp8
    #pragma unroll
    for (int mt = 0; mt < 2; mt++) {
        int r0 = block_row + wm + mt * 16 + (lane >> 2);
        int r1 = r0 + 8;
        float d0 = __ldg(dinv + min(r0, M - 1)) * esc;
        float d1 = __ldg(dinv + min(r1, M - 1)) * esc;
        #pragma unroll
        for (int nt = 0; nt < 4; nt++) {
            int col = wn + nt * 8 + (lane & 3) * 2;
            if (r0 < M)
                *(uint16_t*)(H8 + (size_t)r0 * F + col) =
                    f2_to_e4m3x2(acc[mt][nt][0] * d0, acc[mt][nt][1] * d0);
            if (r1 < M)
                *(uint16_t*)(H8 + (size_t)r1 * F + col) =
                    f2_to_e4m3x2(acc[mt][nt][2] * d1, acc[mt][nt][3] * d1);
        }
    }
}

// ---------------------------------------------------------------------------
// Gather aggregation over prescaled fp8 H' (128B rows):
//   a[c] = (dc/16) * ( sum_{r in N(c)} H'[r] + H'[c] ) + bias
// Warp handles 4 nodes; lane = 4 features (4B load); 8 edges in flight.
// ---------------------------------------------------------------------------
#define NPW 4

__device__ __forceinline__ void tree4_acc(uint32_t u0, uint32_t u1,
                                          uint32_t u2, uint32_t u3, float4& acc) {
    __half2 a0, b0, a1, b1, a2, b2, a3, b3;
    fp8x4_to_h2(u0, a0, b0);
    fp8x4_to_h2(u1, a1, b1);
    fp8x4_to_h2(u2, a2, b2);
    fp8x4_to_h2(u3, a3, b3);
    __half2 sa = __hadd2(__hadd2(a0, a1), __hadd2(a2, a3));
    __half2 sb = __hadd2(__hadd2(b0, b1), __hadd2(b2, b3));
    float2 fa = __half22float2(sa), fb = __half22float2(sb);
    acc.x += fa.x; acc.y += fa.y; acc.z += fb.x; acc.w += fb.y;
}

template <bool FUSE_HEAD>
__global__ void __launch_bounds__(256)
k_agg(const int* __restrict__ start, const int* __restrict__ srow,
      const float* __restrict__ dinv, const uint8_t* __restrict__ H8,
      const float* __restrict__ bias,
      const float* __restrict__ Wl, const float* __restrict__ bl,
      uint8_t* __restrict__ hout8, float* __restrict__ fout, int n) {
    const int lane = threadIdx.x & 31;
    const int warp = (blockIdx.x * blockDim.x + threadIdx.x) >> 5;
    int c0 = warp * NPW;
    if (c0 >= n) return;
    int c_end = min(c0 + NPW, n);

    float4 bv = __ldg((const float4*)bias + lane);
    float4 wv = make_float4(0.f, 0.f, 0.f, 0.f);
    float blv = 0.f;
    if (FUSE_HEAD) { wv = __ldg((const float4*)Wl + lane); blv = __ldg(bl); }

    for (int c = c0; c < c_end; c++) {
        int beg = __ldg(start + c);
        int end = __ldg(start + c + 1);
        float dc = __ldg(dinv + c) * (1.0f / FP8_SCALE);

        uint32_t su = __ldg((const uint32_t*)(H8 + (size_t)c * F) + lane);
        __half2 spa, spb; fp8x4_to_h2(su, spa, spb);
        float2 sfa = __half22float2(spa), sfb = __half22float2(spb);
        float4 acc = make_float4(sfa.x, sfa.y, sfb.x, sfb.y);

        for (int i = beg; i < end; i += 32) {
            int idx = i + lane;
            int rr = __ldcs(srow + (idx < end ? idx : end - 1));
            int cnt = min(end - i, 32);
            int j = 0;
            for (; j + 8 <= cnt; j += 8) {
                int r0 = __shfl_sync(0xFFFFFFFFu, rr, j);
                int r1 = __shfl_sync(0xFFFFFFFFu, rr, j + 1);
                int r2 = __shfl_sync(0xFFFFFFFFu, rr, j + 2);
                int r3 = __shfl_sync(0xFFFFFFFFu, rr, j + 3);
                int r4 = __shfl_sync(0xFFFFFFFFu, rr, j + 4);
                int r5 = __shfl_sync(0xFFFFFFFFu, rr, j + 5);
                int r6 = __shfl_sync(0xFFFFFFFFu, rr, j + 6);
                int r7 = __shfl_sync(0xFFFFFFFFu, rr, j + 7);
                uint32_t u0 = __ldg((const uint32_t*)(H8 + (size_t)r0 * F) + lane);
                uint32_t u1 = __ldg((const uint32_t*)(H8 + (size_t)r1 * F) + lane);
                uint32_t u2 = __ldg((const uint32_t*)(H8 + (size_t)r2 * F) + lane);
                uint32_t u3 = __ldg((const uint32_t*)(H8 + (size_t)r3 * F) + lane);
                uint32_t u4 = __ldg((const uint32_t*)(H8 + (size_t)r4 * F) + lane);
                uint32_t u5 = __ldg((const uint32_t*)(H8 + (size_t)r5 * F) + lane);
                uint32_t u6 = __ldg((const uint32_t*)(H8 + (size_t)r6 * F) + lane);
                uint32_t u7 = __ldg((const uint32_t*)(H8 + (size_t)r7 * F) + lane);
                tree4_acc(u0, u1, u2, u3, acc);
                tree4_acc(u4, u5, u6, u7, acc);
            }
            for (; j + 4 <= cnt; j += 4) {
                int r0 = __shfl_sync(0xFFFFFFFFu, rr, j);
                int r1 = __shfl_sync(0xFFFFFFFFu, rr, j + 1);
                int r2 = __shfl_sync(0xFFFFFFFFu, rr, j + 2);
                int r3 = __shfl_sync(0xFFFFFFFFu, rr, j + 3);
                uint32_t u0 = __ldg((const uint32_t*)(H8 + (size_t)r0 * F) + lane);
                uint32_t u1 = __ldg((const uint32_t*)(H8 + (size_t)r1 * F) + lane);
                uint32_t u2 = __ldg((const uint32_t*)(H8 + (size_t)r2 * F) + lane);
                uint32_t u3 = __ldg((const uint32_t*)(H8 + (size_t)r3 * F) + lane);
                tree4_acc(u0, u1, u2, u3, acc);
            }
            for (; j < cnt; j++) {
                int r0 = __shfl_sync(0xFFFFFFFFu, rr, j);
                uint32_t u0 = __ldg((const uint32_t*)(H8 + (size_t)r0 * F) + lane);
                __half2 pa, pb; fp8x4_to_h2(u0, pa, pb);
                float2 fa = __half22float2(pa), fb = __half22float2(pb);
                acc.x += fa.x; acc.y += fa.y; acc.z += fb.x; acc.w += fb.y;
            }
        }

        float4 o = make_float4(fmaf(dc, acc.x, bv.x), fmaf(dc, acc.y, bv.y),
                               fmaf(dc, acc.z, bv.z), fmaf(dc, acc.w, bv.w));

        if (!FUSE_HEAD) {
            o.x = fmaxf(o.x, 0.f) * FP8_SCALE; o.y = fmaxf(o.y, 0.f) * FP8_SCALE;
            o.z = fmaxf(o.z, 0.f) * FP8_SCALE; o.w = fmaxf(o.w, 0.f) * FP8_SCALE;
            uint32_t lo = f2_to_e4m3x2(o.x, o.y);
            uint32_t hi = f2_to_e4m3x2(o.z, o.w);
            *((uint32_t*)(hout8 + (size_t)c * F) + lane) = lo | (hi << 16);
        } else {
            float s = fmaxf(o.x, 0.f) * wv.x + fmaxf(o.y, 0.f) * wv.y +
                      fmaxf(o.z, 0.f) * wv.z + fmaxf(o.w, 0.f) * wv.w;
            #pragma unroll
            for (int off = 16; off; off >>= 1) s += __shfl_xor_sync(0xFFFFFFFFu, s, off);
            if (lane == 0) {
                float z = s + blv;
                fout[c] = 1.0f / (1.0f + expf(-z));
            }
        }
    }
}

// ---------------------------------------------------------------------------
extern "C" void kernel_launch(void* const* d_in, const int* in_sizes, int n_in,
                              void* d_out, int out_size) {
    const float* x  = (const float*)d_in[0];
    const int*   ei = (const int*)  d_in[1];
    const float* W1 = (const float*)d_in[2];
    const float* b1 = (const float*)d_in[3];
    const float* W2 = (const float*)d_in[4];
    const float* b2 = (const float*)d_in[5];
    const float* Wl = (const float*)d_in[6];
    const float* bl = (const float*)d_in[7];

    int n = in_sizes[0] / F;
    int E = in_sizes[1] / 2;
    const int* rowp = ei;
    const int* colp = ei + E;

    int *cnt, *start, *cursor, *bsum, *boff, *srow;
    float *dinv;
    uint8_t *h8, *a8;
    cudaGetSymbolAddress((void**)&cnt,    g_cnt);
    cudaGetSymbolAddress((void**)&start,  g_start);
    cudaGetSymbolAddress((void**)&cursor, g_cursor);
    cudaGetSymbolAddress((void**)&bsum,   g_bsum);
    cudaGetSymbolAddress((void**)&boff,   g_boff);
    cudaGetSymbolAddress((void**)&srow,   g_srow);
    cudaGetSymbolAddress((void**)&dinv,   g_dinv);
    cudaGetSymbolAddress((void**)&h8,     g_h8);
    cudaGetSymbolAddress((void**)&a8,     g_a8);

    const size_t gemm_smem = (size_t)(2 * 128 * SLD) * sizeof(h16_t);
    cudaFuncSetAttribute((const void*)k_gemm_mma<float>,
                         cudaFuncAttributeMaxDynamicSharedMemorySize, (int)gemm_smem);
    cudaFuncSetAttribute((const void*)k_gemm_mma<uint8_t>,
                         cudaFuncAttributeMaxDynamicSharedMemorySize, (int)gemm_smem);

    // Side stream + events for overlapping the sort chain with GEMM1.
    static cudaStream_t s2 = nullptr;
    static cudaEvent_t evA = nullptr, evB = nullptr;
    static int init_tried = 0;
    if (!init_tried) {
        init_tried = 1;
        if (cudaStreamCreateWithFlags(&s2, cudaStreamNonBlocking) != cudaSuccess) s2 = nullptr;
        if (cudaEventCreateWithFlags(&evA, cudaEventDisableTiming) != cudaSuccess) evA = nullptr;
        if (cudaEventCreateWithFlags(&evB, cudaEventDisableTiming) != cudaSuccess) evB = nullptr;
    }
    bool par = (s2 != nullptr) && (evA != nullptr) && (evB != nullptr);

    int nb = (n + SCAN_BLK - 1) / SCAN_BLK;
    int gemm_grid = (n + 127) / 128;
    int agg_grid  = ((n + NPW - 1) / NPW * 32 + 255) / 256;

    // --- degree + dinv (cnt zeroed via memset node) ---
    cudaMemsetAsync(cnt, 0, (size_t)n * sizeof(int), 0);
    k_hist<<<(E + 255) / 256, 256>>>(colp, cnt, E);
    k_dinv<<<(n + 255) / 256, 256>>>(cnt, dinv, n);

    if (par) {
        cudaEventRecord(evA, 0);
        cudaStreamWaitEvent(s2, evA, 0);
        k_blocksum<<<nb, 256, 0, s2>>>(cnt, bsum, n);
        k_gemm_mma<float><<<gemm_grid, 512, gemm_smem>>>(x, W1, dinv, h8, FP8_SCALE, n);
        k_scanbsum  <<<1, 256, 0, s2>>>(bsum, boff, start, nb, n);
        k_writestart<<<nb, 256, 0, s2>>>(cnt, boff, start, cursor, n);
        k_scatter   <<<(E + 255) / 256, 256, 0, s2>>>(rowp, colp, cursor, srow, E);
        cudaEventRecord(evB, s2);
        cudaStreamWaitEvent(0, evB, 0);
    } else {
        k_blocksum  <<<nb, 256>>>(cnt, bsum, n);
        k_gemm_mma<float><<<gemm_grid, 512, gemm_smem>>>(x, W1, dinv, h8, FP8_SCALE, n);
        k_scanbsum  <<<1, 256>>>(bsum, boff, start, nb, n);
        k_writestart<<<nb, 256>>>(cnt, boff, start, cursor, n);
        k_scatter   <<<(E + 255) / 256, 256>>>(rowp, colp, cursor, srow, E);
    }

    // --- layer 1 agg (fp8 gather) -> fp8 a8 (x16) ---
    k_agg<false><<<agg_grid, 256>>>(start, srow, dinv, h8, b1, nullptr, nullptr, a8, nullptr, n);

    // --- layer 2: A carries x16 -> esc = 1.0 keeps H8 = 16*dinv*(a@W2) ---
    k_gemm_mma<uint8_t><<<gemm_grid, 512, gemm_smem>>>(a8, W2, dinv, h8, 1.0f, n);
    k_agg<true><<<agg_grid, 256>>>(start, srow, dinv, h8, b2, Wl, bl, nullptr, (float*)d_out, n);
}